// round 15
// baseline (speedup 1.0000x reference)
#include <cuda_runtime.h>
#include <cuda_bf16.h>
#include <cstdint>

#define B_   64
#define T_   4096
#define NIN  64
#define U_   128
#define NOUT 64
#define CCH  64
#define LCH  64
#define HT   2048
#define HCH  32

#define SSTRIDE 136
#define MROWS   64

// ---------------------------------------------------------------------------
// Static device scratch
// ---------------------------------------------------------------------------
__device__ float g_Z[B_ * HT * U_];
__device__ float g_S[B_ * HT * U_];
__device__ float g_carry[B_ * CCH * U_];
__device__ float g_A2[U_ * U_], g_A4[U_ * U_], g_A8[U_ * U_];
__device__ float g_A16[U_ * U_], g_A32[U_ * U_], g_A64[U_ * U_];

__device__ __align__(16) unsigned short g_MT_hi[128 * 128],  g_MT_lo[128 * 128];
__device__ __align__(16) unsigned short g_WT_hi[32 * 128 * 128], g_WT_lo[32 * 128 * 128];
__device__ __align__(16) unsigned short g_YB_hi[128 * 128],  g_YB_lo[128 * 128];
__device__ __align__(16) unsigned short g_KCT_hi[64 * 128],  g_KCT_lo[64 * 128];

// ---------------------------------------------------------------------------
// f32x2 helpers (scan path)
// ---------------------------------------------------------------------------
__device__ __forceinline__ unsigned long long ffma2(unsigned long long a,
                                                    unsigned long long b,
                                                    unsigned long long c) {
    unsigned long long d;
    asm("fma.rn.f32x2 %0, %1, %2, %3;" : "=l"(d) : "l"(a), "l"(b), "l"(c));
    return d;
}
__device__ __forceinline__ unsigned long long dup2(float v) {
    unsigned long long r;
    asm("mov.b64 %0, {%1, %1};" : "=l"(r) : "f"(v));
    return r;
}
__device__ __forceinline__ unsigned long long pack2(float x, float y) {
    unsigned long long r;
    asm("mov.b64 %0, {%1, %2};" : "=l"(r) : "f"(x), "f"(y));
    return r;
}
__device__ __forceinline__ float2 unpack2(unsigned long long v) {
    float2 f;
    asm("mov.b64 {%0, %1}, %2;" : "=f"(f.x), "=f"(f.y) : "l"(v));
    return f;
}

// ---------------------------------------------------------------------------
// mma.sync / ldmatrix helpers
// ---------------------------------------------------------------------------
__device__ __forceinline__ uint32_t smem_u32(const void* p) {
    uint32_t a;
    asm("{ .reg .u64 t; cvta.to.shared.u64 t, %1; cvt.u32.u64 %0, t; }"
        : "=r"(a) : "l"(p));
    return a;
}

__device__ __forceinline__ void ldsm4(uint32_t addr, uint32_t r[4]) {
    asm volatile("ldmatrix.sync.aligned.m8n8.x4.shared.b16 {%0,%1,%2,%3}, [%4];"
                 : "=r"(r[0]), "=r"(r[1]), "=r"(r[2]), "=r"(r[3]) : "r"(addr));
}

__device__ __forceinline__ void mma16816(float c[4], const uint32_t a[4],
                                         const uint32_t b[2]) {
    asm volatile(
        "mma.sync.aligned.m16n8k16.row.col.f32.bf16.bf16.f32 "
        "{%0,%1,%2,%3}, {%4,%5,%6,%7}, {%8,%9}, {%0,%1,%2,%3};"
        : "+f"(c[0]), "+f"(c[1]), "+f"(c[2]), "+f"(c[3])
        : "r"(a[0]), "r"(a[1]), "r"(a[2]), "r"(a[3]), "r"(b[0]), "r"(b[1]));
}

__device__ __forceinline__ void split_bf16(float v, unsigned short& h, unsigned short& l) {
    __nv_bfloat16 hb = __float2bfloat16(v);
    float r = v - __bfloat162float(hb);
    __nv_bfloat16 lb = __float2bfloat16(r);
    h = *reinterpret_cast<unsigned short*>(&hb);
    l = *reinterpret_cast<unsigned short*>(&lb);
}

// ---------------------------------------------------------------------------
// setup_kernel: grid=3, 1024 threads, 128KB dyn smem. Replaces 9 launches.
//  CTA0: matsq chain A2..A64 (smem-resident, serial squarings)
//  CTA1: M = [[KT@A],[KT]] then split -> g_MT
//  CTA2: YB rows 0-63 = split(CyT); rows 64-127 = split(A@CyT); KCT = split(KT@CyT)
// ---------------------------------------------------------------------------
__global__ __launch_bounds__(1024) void setup_kernel(const float* __restrict__ AT,
                                                     const float* __restrict__ KT,
                                                     const float* __restrict__ CyT) {
    extern __shared__ float sm[];
    const int t = threadIdx.x;

    if (blockIdx.x == 0) {
        float* cur = sm;
        float* nxt = sm + 16384;
        for (int i = t; i < 16384; i += 1024) cur[i] = AT[i];
        __syncthreads();
        float* const outs[6] = {g_A2, g_A4, g_A8, g_A16, g_A32, g_A64};
        const int u = t & 127, rb = t >> 7;
#pragma unroll 1
        for (int s = 0; s < 6; s++) {
#pragma unroll 1
            for (int j = 0; j < 16; j++) {
                const int r = rb * 16 + j;
                float a0 = 0.f, a1 = 0.f, a2 = 0.f, a3 = 0.f;
#pragma unroll
                for (int k = 0; k < 128; k += 4) {
                    a0 = fmaf(cur[r * 128 + k + 0], cur[(k + 0) * 128 + u], a0);
                    a1 = fmaf(cur[r * 128 + k + 1], cur[(k + 1) * 128 + u], a1);
                    a2 = fmaf(cur[r * 128 + k + 2], cur[(k + 2) * 128 + u], a2);
                    a3 = fmaf(cur[r * 128 + k + 3], cur[(k + 3) * 128 + u], a3);
                }
                nxt[r * 128 + u] = (a0 + a1) + (a2 + a3);
            }
            __syncthreads();
            for (int i = t; i < 16384; i += 1024) outs[s][i] = nxt[i];
            float* tmp = cur; cur = nxt; nxt = tmp;
            __syncthreads();
        }
    } else if (blockIdx.x == 1) {
        float* a_sh = sm;           // A
        float* m_sh = sm + 16384;   // M
        for (int i = t; i < 16384; i += 1024) a_sh[i] = AT[i];
        __syncthreads();
        {
            const int u = t & 127, rb = t >> 7;
#pragma unroll 1
            for (int j = 0; j < 8; j++) {
                const int r = rb * 8 + j;   // 0..63
                float a0 = 0.f, a1 = 0.f, a2 = 0.f, a3 = 0.f;
#pragma unroll
                for (int k = 0; k < 128; k += 4) {
                    a0 = fmaf(KT[r * 128 + k + 0], a_sh[(k + 0) * 128 + u], a0);
                    a1 = fmaf(KT[r * 128 + k + 1], a_sh[(k + 1) * 128 + u], a1);
                    a2 = fmaf(KT[r * 128 + k + 2], a_sh[(k + 2) * 128 + u], a2);
                    a3 = fmaf(KT[r * 128 + k + 3], a_sh[(k + 3) * 128 + u], a3);
                }
                m_sh[r * 128 + u] = (a0 + a1) + (a2 + a3);
                m_sh[(64 + r) * 128 + u] = KT[r * 128 + u];
            }
        }
        __syncthreads();
        for (int idx = t; idx < 16384; idx += 1024) {
            const int nl = idx >> 7, k = idx & 127;
            unsigned short h, l;
            split_bf16(m_sh[k * 128 + nl], h, l);
            g_MT_hi[idx] = h;
            g_MT_lo[idx] = l;
        }
    } else {
        float* cy = sm;             // CyT [128][64]
        for (int i = t; i < 8192; i += 1024) cy[i] = CyT[i];
        __syncthreads();
        // YB rows 0-63: split(CyT)
        for (int idx = t; idx < 8192; idx += 1024) {
            const int nl = idx >> 7, k = idx & 127;
            unsigned short h, l;
            split_bf16(cy[k * 64 + nl], h, l);
            g_YB_hi[idx] = h;
            g_YB_lo[idx] = l;
        }
        // YB rows 64-127: split(A@CyT)
        for (int idx = t; idx < 8192; idx += 1024) {
            const int nl = idx >> 7, k = idx & 127;
            float a0 = 0.f, a1 = 0.f, a2 = 0.f, a3 = 0.f;
#pragma unroll
            for (int m = 0; m < 128; m += 4) {
                a0 = fmaf(AT[k * 128 + m + 0], cy[(m + 0) * 64 + nl], a0);
                a1 = fmaf(AT[k * 128 + m + 1], cy[(m + 1) * 64 + nl], a1);
                a2 = fmaf(AT[k * 128 + m + 2], cy[(m + 2) * 64 + nl], a2);
                a3 = fmaf(AT[k * 128 + m + 3], cy[(m + 3) * 64 + nl], a3);
            }
            unsigned short h, l;
            split_bf16((a0 + a1) + (a2 + a3), h, l);
            g_YB_hi[8192 + idx] = h;
            g_YB_lo[8192 + idx] = l;
        }
        // KCT: split(KT@CyT) for k<64, zero for k>=64
        for (int idx = t; idx < 8192; idx += 1024) {
            const int nl = idx >> 7, k = idx & 127;
            unsigned short h = 0, l = 0;
            if (k < 64) {
                float a0 = 0.f, a1 = 0.f, a2 = 0.f, a3 = 0.f;
#pragma unroll
                for (int m = 0; m < 128; m += 4) {
                    a0 = fmaf(KT[k * 128 + m + 0], cy[(m + 0) * 64 + nl], a0);
                    a1 = fmaf(KT[k * 128 + m + 1], cy[(m + 1) * 64 + nl], a1);
                    a2 = fmaf(KT[k * 128 + m + 2], cy[(m + 2) * 64 + nl], a2);
                    a3 = fmaf(KT[k * 128 + m + 3], cy[(m + 3) * 64 + nl], a3);
                }
                split_bf16((a0 + a1) + (a2 + a3), h, l);
            }
            g_KCT_hi[idx] = h;
            g_KCT_lo[idx] = l;
        }
    }
}

// ---------------------------------------------------------------------------
// hgemm (verified R13/R14): D[64, NTILE] = A[64,128] @ B^T, split-bf16.
// MODE 0: write g_Z.  MODE 1: y parity epilogue (even-s +=, odd-s =).
// MODE 4: y even = x@KC (write, first).  MODE 5: odd += S@CyT, even+2 += S@ACyT.
// ---------------------------------------------------------------------------
template <int NTILE, int MODE>
__global__ __launch_bounds__(256) void hgemm(const float* __restrict__ gA,
                                             const unsigned short* __restrict__ gBhi,
                                             const unsigned short* __restrict__ gBlo,
                                             float* __restrict__ out) {
    extern __shared__ __align__(16) char smc[];
    constexpr int A_ELE = MROWS * SSTRIDE;
    constexpr int B_ELE = NTILE * SSTRIDE;
    unsigned short* sAhi = (unsigned short*)smc;
    unsigned short* sAlo = sAhi + A_ELE;
    unsigned short* sBhi = sAlo + A_ELE;
    unsigned short* sBlo = sBhi + B_ELE;
    const uint32_t aAhi = smem_u32(sAhi), aAlo = smem_u32(sAlo);
    const uint32_t aBhi = smem_u32(sBhi), aBlo = smem_u32(sBlo);

    const int t = threadIdx.x;
    const int lane = t & 31, w = t >> 5;

    {
        const float4* Atile = (const float4*)(gA + (size_t)blockIdx.x * (MROWS * 128));
#pragma unroll
        for (int j = 0; j < 8; j++) {
            const int f = j * 256 + t;
            const float4 v = Atile[f];
            const int row = f >> 5, c = (f & 31) * 4;
            unsigned short h0, l0, h1, l1, h2, l2, h3, l3;
            split_bf16(v.x, h0, l0);
            split_bf16(v.y, h1, l1);
            split_bf16(v.z, h2, l2);
            split_bf16(v.w, h3, l3);
            const unsigned long long hh =
                (unsigned long long)h0 | ((unsigned long long)h1 << 16) |
                ((unsigned long long)h2 << 32) | ((unsigned long long)h3 << 48);
            const unsigned long long ll =
                (unsigned long long)l0 | ((unsigned long long)l1 << 16) |
                ((unsigned long long)l2 << 32) | ((unsigned long long)l3 << 48);
            *(unsigned long long*)(sAhi + row * SSTRIDE + c) = hh;
            *(unsigned long long*)(sAlo + row * SSTRIDE + c) = ll;
        }
    }
    {
        const size_t boff = (MODE == 1) ? (size_t)blockIdx.y * (NTILE * 128) : 0;
        const uint4* sh = (const uint4*)(gBhi + boff);
        const uint4* sl = (const uint4*)(gBlo + boff);
#pragma unroll
        for (int j = 0; j < NTILE / 16; j++) {
            const int f = j * 256 + t;
            const int row = f >> 4, c = (f & 15) * 8;
            *(uint4*)(sBhi + row * SSTRIDE + c) = sh[f];
            *(uint4*)(sBlo + row * SSTRIDE + c) = sl[f];
        }
    }
    __syncthreads();

    const int wm = w & 1, wn = w >> 1;
    const int m0w = wm * 32, n0w = wn * (NTILE / 4);
    constexpr int NF = NTILE / 32;

    float acc[2][NF][4];
#pragma unroll
    for (int i = 0; i < 2; i++)
#pragma unroll
        for (int j = 0; j < NF; j++)
#pragma unroll
            for (int q = 0; q < 4; q++) acc[i][j][q] = 0.f;

    const int aRow = lane & 15, aCol = (lane >> 4) * 8;
    const int bRow = (lane & 7) + ((lane >> 4) << 3), bCol = ((lane >> 3) & 1) * 8;

#pragma unroll
    for (int ks = 0; ks < 8; ks++) {
        const int k0 = ks * 16;
        uint32_t ahi[2][4], alo[2][4];
#pragma unroll
        for (int mf = 0; mf < 2; mf++) {
            const uint32_t off =
                (uint32_t)(((m0w + mf * 16 + aRow) * SSTRIDE + k0 + aCol) * 2);
            ldsm4(aAhi + off, ahi[mf]);
            ldsm4(aAlo + off, alo[mf]);
        }
        uint32_t bhi[NF][2], blo[NF][2];
#pragma unroll
        for (int nf2 = 0; nf2 < NF / 2; nf2++) {
            const uint32_t off =
                (uint32_t)(((n0w + nf2 * 16 + bRow) * SSTRIDE + k0 + bCol) * 2);
            uint32_t r[4];
            ldsm4(aBhi + off, r);
            bhi[nf2 * 2][0] = r[0]; bhi[nf2 * 2][1] = r[1];
            bhi[nf2 * 2 + 1][0] = r[2]; bhi[nf2 * 2 + 1][1] = r[3];
            ldsm4(aBlo + off, r);
            blo[nf2 * 2][0] = r[0]; blo[nf2 * 2][1] = r[1];
            blo[nf2 * 2 + 1][0] = r[2]; blo[nf2 * 2 + 1][1] = r[3];
        }
#pragma unroll
        for (int mf = 0; mf < 2; mf++)
#pragma unroll
            for (int nf = 0; nf < NF; nf++) {
                mma16816(acc[mf][nf], ahi[mf], bhi[nf]);
                mma16816(acc[mf][nf], ahi[mf], blo[nf]);
                mma16816(acc[mf][nf], alo[mf], bhi[nf]);
            }
    }

#pragma unroll
    for (int mf = 0; mf < 2; mf++) {
#pragma unroll
        for (int half = 0; half < 2; half++) {
            const int rloc = m0w + mf * 16 + (lane >> 2) + half * 8;
            const int r = blockIdx.x * MROWS + rloc;

            if (MODE == 5) {
                const int b = r >> 11, i = r & (HT - 1);
                const bool lastI = ((i & (HCH - 1)) == (HCH - 1));
                float* base1 = out + ((size_t)b * T_ + 2 * i + 1) * NOUT;
                float* base2 = out + ((size_t)b * T_ + 2 * i + 2) * NOUT;
#pragma unroll
                for (int nf = 0; nf < NF; nf++) {
                    const int n = n0w + nf * 8 + (lane & 3) * 2;
                    float* p;
                    if (n < 64) p = base1 + n;
                    else { if (lastI) continue; p = base2 + (n - 64); }
                    float2 v = make_float2(acc[mf][nf][half * 2],
                                           acc[mf][nf][half * 2 + 1]);
                    float2 e = *(float2*)p;
                    v.x += e.x; v.y += e.y;
                    *(float2*)p = v;
                }
                continue;
            }

            float* rowp;
            if (MODE == 0) {
                rowp = out + (size_t)r * 128;
            } else if (MODE == 1) {
                rowp = out + (size_t)r * 4096 + blockIdx.y * 128;
            } else {  // MODE 4
                const int b = r >> 11, i = r & (HT - 1);
                rowp = out + ((size_t)b * T_ + 2 * i) * NOUT;
            }
#pragma unroll
            for (int nf = 0; nf < NF; nf++) {
                const int cc = n0w + nf * 8 + (lane & 3) * 2;
                float2 v = make_float2(acc[mf][nf][half * 2],
                                       acc[mf][nf][half * 2 + 1]);
                float* p = rowp + cc;
                if (MODE == 1) {
                    if (((n0w + nf * 8) & 64) == 0) {   // even-s col: mode4 wrote
                        float2 e = *(float2*)p;
                        v.x += e.x; v.y += e.y;
                    }
                }
                *(float2*)p = v;
            }
        }
    }
}

// ---------------------------------------------------------------------------
// scan (verified): e_i = Z_i + e_{i-1}@A2, 32 steps, 16 batches/CTA
// ---------------------------------------------------------------------------
__global__ __launch_bounds__(128, 2) void scan_kernel() {
    const int c = blockIdx.x, bg = blockIdx.y, u = threadIdx.x;
    const int b0 = bg * 16;
    __shared__ __align__(16) float s_sh[2][U_ * 16];

    float at2[U_];
#pragma unroll
    for (int k = 0; k < U_; k++) at2[k] = g_A2[k * U_ + u];
#pragma unroll
    for (int j = 0; j < 16; j++) s_sh[0][u * 16 + j] = 0.f;
    __syncthreads();

    const int i0 = c * HCH;
    float zc[16];
#pragma unroll
    for (int j = 0; j < 16; j++)
        zc[j] = g_Z[((size_t)(b0 + j) * HT + i0) * U_ + u];

    int p = 0;
#pragma unroll 1
    for (int it = 0; it < HCH; it++) {
        const int i = i0 + it;
        float zn[16];
        if (it < HCH - 1) {
#pragma unroll
            for (int j = 0; j < 16; j++)
                zn[j] = g_Z[((size_t)(b0 + j) * HT + i + 1) * U_ + u];
        } else {
#pragma unroll
            for (int j = 0; j < 16; j++) zn[j] = 0.f;
        }

        unsigned long long acc[8];
#pragma unroll
        for (int q = 0; q < 8; q++) acc[q] = pack2(zc[2 * q], zc[2 * q + 1]);

#pragma unroll
        for (int k = 0; k < U_; k++) {
            const unsigned long long av = dup2(at2[k]);
            const ulonglong2 s0 = *(const ulonglong2*)&s_sh[p][k * 16 + 0];
            const ulonglong2 s1 = *(const ulonglong2*)&s_sh[p][k * 16 + 4];
            const ulonglong2 s2 = *(const ulonglong2*)&s_sh[p][k * 16 + 8];
            const ulonglong2 s3 = *(const ulonglong2*)&s_sh[p][k * 16 + 12];
            acc[0] = ffma2(s0.x, av, acc[0]);
            acc[1] = ffma2(s0.y, av, acc[1]);
            acc[2] = ffma2(s1.x, av, acc[2]);
            acc[3] = ffma2(s1.y, av, acc[3]);
            acc[4] = ffma2(s2.x, av, acc[4]);
            acc[5] = ffma2(s2.y, av, acc[5]);
            acc[6] = ffma2(s3.x, av, acc[6]);
            acc[7] = ffma2(s3.y, av, acc[7]);
        }

        const int q = p ^ 1;
        float2 f0 = unpack2(acc[0]), f1 = unpack2(acc[1]);
        float2 f2 = unpack2(acc[2]), f3 = unpack2(acc[3]);
        float2 f4 = unpack2(acc[4]), f5 = unpack2(acc[5]);
        float2 f6 = unpack2(acc[6]), f7 = unpack2(acc[7]);
        {
            float4* dst = (float4*)&s_sh[q][u * 16];
            dst[0] = make_float4(f0.x, f0.y, f1.x, f1.y);
            dst[1] = make_float4(f2.x, f2.y, f3.x, f3.y);
            dst[2] = make_float4(f4.x, f4.y, f5.x, f5.y);
            dst[3] = make_float4(f6.x, f6.y, f7.x, f7.y);
        }
        g_S[((size_t)(b0 + 0)  * HT + i) * U_ + u] = f0.x;
        g_S[((size_t)(b0 + 1)  * HT + i) * U_ + u] = f0.y;
        g_S[((size_t)(b0 + 2)  * HT + i) * U_ + u] = f1.x;
        g_S[((size_t)(b0 + 3)  * HT + i) * U_ + u] = f1.y;
        g_S[((size_t)(b0 + 4)  * HT + i) * U_ + u] = f2.x;
        g_S[((size_t)(b0 + 5)  * HT + i) * U_ + u] = f2.y;
        g_S[((size_t)(b0 + 6)  * HT + i) * U_ + u] = f3.x;
        g_S[((size_t)(b0 + 7)  * HT + i) * U_ + u] = f3.y;
        g_S[((size_t)(b0 + 8)  * HT + i) * U_ + u] = f4.x;
        g_S[((size_t)(b0 + 9)  * HT + i) * U_ + u] = f4.y;
        g_S[((size_t)(b0 + 10) * HT + i) * U_ + u] = f5.x;
        g_S[((size_t)(b0 + 11) * HT + i) * U_ + u] = f5.y;
        g_S[((size_t)(b0 + 12) * HT + i) * U_ + u] = f6.x;
        g_S[((size_t)(b0 + 13) * HT + i) * U_ + u] = f6.y;
        g_S[((size_t)(b0 + 14) * HT + i) * U_ + u] = f7.x;
        g_S[((size_t)(b0 + 15) * HT + i) * U_ + u] = f7.y;
        __syncthreads();

        p = q;
#pragma unroll
        for (int j = 0; j < 16; j++) zc[j] = zn[j];
    }
}

// ---------------------------------------------------------------------------
// tail_kernel: grid=128, 512 threads, 64KB dyn smem.
//  blocks 0-63:  wbuild body (W[s] = A^(s+1)@CyT, direct split write)
//  blocks 64-127: pass2 body (carry scan), A64 staged in dyn smem
// ---------------------------------------------------------------------------
__global__ __launch_bounds__(512) void tail_kernel(const float* __restrict__ A1,
                                                   const float* __restrict__ CyT) {
    extern __shared__ float V[];
    const int tid = threadIdx.x;

    if (blockIdx.x < 64) {
        float* cur = V;
        float* nxt = V + 8192;
        const int s = blockIdx.x;
        const int n = s + 1;
        const int o = tid & 63, kg = tid >> 6;

        for (int i = tid; i < U_ * NOUT; i += 512) cur[i] = CyT[i];
        __syncthreads();

#pragma unroll 1
        for (int b = 0; b < 7; b++) {
            if (!((n >> b) & 1)) continue;
            const float* P = (b == 0) ? A1
                           : (b == 1) ? g_A2  : (b == 2) ? g_A4
                           : (b == 3) ? g_A8  : (b == 4) ? g_A16
                           : (b == 5) ? g_A32 : g_A64;
#pragma unroll 1
            for (int i = 0; i < 16; i++) {
                const int k = kg * 16 + i;
                float a0 = 0.f, a1 = 0.f, a2 = 0.f, a3 = 0.f;
#pragma unroll
                for (int m = 0; m < U_; m += 4) {
                    a0 = fmaf(P[k * U_ + m + 0], cur[(m + 0) * 64 + o], a0);
                    a1 = fmaf(P[k * U_ + m + 1], cur[(m + 1) * 64 + o], a1);
                    a2 = fmaf(P[k * U_ + m + 2], cur[(m + 2) * 64 + o], a2);
                    a3 = fmaf(P[k * U_ + m + 3], cur[(m + 3) * 64 + o], a3);
                }
                nxt[k * 64 + o] = (a0 + a1) + (a2 + a3);
            }
            __syncthreads();
            float* tmp = cur; cur = nxt; nxt = tmp;
        }

        {
            unsigned short* th = g_WT_hi + (size_t)(s >> 1) * 16384;
            unsigned short* tl = g_WT_lo + (size_t)(s >> 1) * 16384;
            const int nbase = (s & 1) * 64;
#pragma unroll 1
            for (int idx = tid; idx < 8192; idx += 512) {
                const int k = idx & 127, oo = idx >> 7;
                unsigned short h, l;
                split_bf16(cur[k * 64 + oo], h, l);
                th[(nbase + oo) * 128 + k] = h;
                tl[(nbase + oo) * 128 + k] = l;
            }
        }
    } else {
        // pass2: A64 staged in dyn smem; ss in static smem
        __shared__ float ss[2][U_];
        float* a64 = V;  // 16384 floats
        const int b = blockIdx.x - 64;
        const int u = tid;
        const bool act = (u < U_);

        for (int i = tid; i < 16384; i += 512) a64[i] = g_A64[i];

        float su = 0.f, e = 0.f;
        if (act) {
            e = g_S[((size_t)b * HT + (HCH - 1)) * U_ + u];
            ss[0][u] = 0.f;
        }
        __syncthreads();

        int p = 0;
#pragma unroll 1
        for (int c = 0; c < CCH; c++) {
            if (act) {
                g_carry[((size_t)b * CCH + c) * U_ + u] = su;
                float a0 = e, a1 = 0.f, a2 = 0.f, a3 = 0.f;
                if (c < CCH - 1)
                    e = g_S[((size_t)b * HT + (c + 1) * HCH + (HCH - 1)) * U_ + u];
#pragma unroll
                for (int k = 0; k < U_; k += 4) {
                    a0 = fmaf(ss[p][k + 0], a64[(k + 0) * U_ + u], a0);
                    a1 = fmaf(ss[p][k + 1], a64[(k + 1) * U_ + u], a1);
                    a2 = fmaf(ss[p][k + 2], a64[(k + 2) * U_ + u], a2);
                    a3 = fmaf(ss[p][k + 3], a64[(k + 3) * U_ + u], a3);
                }
                su = (a0 + a1) + (a2 + a3);
                ss[p ^ 1][u] = su;
            }
            __syncthreads();
            p ^= 1;
        }
    }
}

// ---------------------------------------------------------------------------
// Launch: 7 launches total.  #4 = scan_kernel (ncu-profiled slot).
// ---------------------------------------------------------------------------
extern "C" void kernel_launch(void* const* d_in, const int* in_sizes, int n_in,
                              void* d_out, int out_size) {
    const float* x   = (const float*)d_in[0];
    const float* AT  = (const float*)d_in[1];
    const float* KT  = (const float*)d_in[2];
    const float* CyT = (const float*)d_in[3];
    float* y = (float*)d_out;

    float *pZ, *pS, *pCar;
    unsigned short *MTh, *MTl, *WTh, *WTl, *YBh, *YBl, *KCTh, *KCTl;
    cudaGetSymbolAddress((void**)&pZ,  g_Z);
    cudaGetSymbolAddress((void**)&pS,  g_S);
    cudaGetSymbolAddress((void**)&pCar, g_carry);
    cudaGetSymbolAddress((void**)&MTh, g_MT_hi);  cudaGetSymbolAddress((void**)&MTl, g_MT_lo);
    cudaGetSymbolAddress((void**)&WTh, g_WT_hi);  cudaGetSymbolAddress((void**)&WTl, g_WT_lo);
    cudaGetSymbolAddress((void**)&YBh, g_YB_hi);  cudaGetSymbolAddress((void**)&YBl, g_YB_lo);
    cudaGetSymbolAddress((void**)&KCTh, g_KCT_hi); cudaGetSymbolAddress((void**)&KCTl, g_KCT_lo);

    const int SM128 = (2 * MROWS * SSTRIDE + 2 * 128 * SSTRIDE) * 2;  // 104448
    const int SM64  = (2 * MROWS * SSTRIDE + 2 * 64 * SSTRIDE) * 2;   // 69632
    cudaFuncSetAttribute(setup_kernel, cudaFuncAttributeMaxDynamicSharedMemorySize, 131072);
    cudaFuncSetAttribute(hgemm<128, 0>, cudaFuncAttributeMaxDynamicSharedMemorySize, SM128);
    cudaFuncSetAttribute(hgemm<128, 1>, cudaFuncAttributeMaxDynamicSharedMemorySize, SM128);
    cudaFuncSetAttribute(hgemm<128, 5>, cudaFuncAttributeMaxDynamicSharedMemorySize, SM128);
    cudaFuncSetAttribute(hgemm<64, 4>,  cudaFuncAttributeMaxDynamicSharedMemorySize, SM64);
    cudaFuncSetAttribute(tail_kernel, cudaFuncAttributeMaxDynamicSharedMemorySize, 65536);

    setup_kernel<<<3, 1024, 131072>>>(AT, KT, CyT);            // 1
    hgemm<64, 4><<<2048, 256, SM64>>>(x, KCTh, KCTl, y);       // 2 (writes y even)
    hgemm<128, 0><<<2048, 256, SM128>>>(x, MTh, MTl, pZ);      // 3 (zbuild)
    scan_kernel<<<dim3(CCH, 4), 128>>>();                      // 4 <- ncu
    tail_kernel<<<128, 512, 65536>>>(AT, CyT);                 // 5 (wbuild + pass2)
    hgemm<128, 1><<<dim3(64, 32), 256, SM128>>>(pCar, WTh, WTl, y);  // 6 (parity fixup)
    hgemm<128, 5><<<2048, 256, SM128>>>(pS, YBh, YBl, y);      // 7 (+= odd & even+2)
}

// round 16
// speedup vs baseline: 1.4274x; 1.4274x over previous
#include <cuda_runtime.h>
#include <cuda_bf16.h>
#include <cstdint>

#define B_   64
#define T_   4096
#define NIN  64
#define U_   128
#define NOUT 64
#define CCH  64
#define LCH  64
#define HT   2048
#define HCH  32

#define SSTRIDE 136
#define MROWS   64

// ---------------------------------------------------------------------------
// Static device scratch
// ---------------------------------------------------------------------------
__device__ float g_Z[B_ * HT * U_];
__device__ float g_S[B_ * HT * U_];
__device__ float g_carry[B_ * CCH * U_];
__device__ float g_M[U_ * U_];
__device__ float g_KC[NIN * NOUT];
__device__ float g_ACyT[U_ * NOUT];
__device__ float g_A2[U_ * U_], g_A4[U_ * U_], g_A8[U_ * U_];
__device__ float g_A16[U_ * U_], g_A32[U_ * U_], g_A64[U_ * U_];

__device__ __align__(16) unsigned short g_MT_hi[128 * 128],  g_MT_lo[128 * 128];
__device__ __align__(16) unsigned short g_WT_hi[32 * 128 * 128], g_WT_lo[32 * 128 * 128];
__device__ __align__(16) unsigned short g_YB_hi[128 * 128],  g_YB_lo[128 * 128];
__device__ __align__(16) unsigned short g_KCT_hi[64 * 128],  g_KCT_lo[64 * 128];

// ---------------------------------------------------------------------------
// f32x2 helpers
// ---------------------------------------------------------------------------
__device__ __forceinline__ unsigned long long ffma2(unsigned long long a,
                                                    unsigned long long b,
                                                    unsigned long long c) {
    unsigned long long d;
    asm("fma.rn.f32x2 %0, %1, %2, %3;" : "=l"(d) : "l"(a), "l"(b), "l"(c));
    return d;
}
__device__ __forceinline__ unsigned long long dup2(float v) {
    unsigned long long r;
    asm("mov.b64 %0, {%1, %1};" : "=l"(r) : "f"(v));
    return r;
}
__device__ __forceinline__ unsigned long long pack2(float x, float y) {
    unsigned long long r;
    asm("mov.b64 %0, {%1, %2};" : "=l"(r) : "f"(x), "f"(y));
    return r;
}
__device__ __forceinline__ float2 unpack2(unsigned long long v) {
    float2 f;
    asm("mov.b64 {%0, %1}, %2;" : "=f"(f.x), "=f"(f.y) : "l"(v));
    return f;
}

// ---------------------------------------------------------------------------
// mma.sync / ldmatrix helpers
// ---------------------------------------------------------------------------
__device__ __forceinline__ uint32_t smem_u32(const void* p) {
    uint32_t a;
    asm("{ .reg .u64 t; cvta.to.shared.u64 t, %1; cvt.u32.u64 %0, t; }"
        : "=r"(a) : "l"(p));
    return a;
}

__device__ __forceinline__ void ldsm4(uint32_t addr, uint32_t r[4]) {
    asm volatile("ldmatrix.sync.aligned.m8n8.x4.shared.b16 {%0,%1,%2,%3}, [%4];"
                 : "=r"(r[0]), "=r"(r[1]), "=r"(r[2]), "=r"(r[3]) : "r"(addr));
}

__device__ __forceinline__ void mma16816(float c[4], const uint32_t a[4],
                                         const uint32_t b[2]) {
    asm volatile(
        "mma.sync.aligned.m16n8k16.row.col.f32.bf16.bf16.f32 "
        "{%0,%1,%2,%3}, {%4,%5,%6,%7}, {%8,%9}, {%0,%1,%2,%3};"
        : "+f"(c[0]), "+f"(c[1]), "+f"(c[2]), "+f"(c[3])
        : "r"(a[0]), "r"(a[1]), "r"(a[2]), "r"(a[3]), "r"(b[0]), "r"(b[1]));
}

__device__ __forceinline__ void split_bf16(float v, unsigned short& h, unsigned short& l) {
    __nv_bfloat16 hb = __float2bfloat16(v);
    float r = v - __bfloat162float(hb);
    __nv_bfloat16 lb = __float2bfloat16(r);
    h = *reinterpret_cast<unsigned short*>(&hb);
    l = *reinterpret_cast<unsigned short*>(&lb);
}

// ---------------------------------------------------------------------------
// prepB (small matrices)
// ---------------------------------------------------------------------------
__global__ __launch_bounds__(256) void prepB(const float* __restrict__ src,
                                             int Ksrc, int Nsrc,
                                             unsigned short* __restrict__ dhi,
                                             unsigned short* __restrict__ dlo,
                                             int ntileRows) {
    const int nt = blockIdx.x;
    const int elems = ntileRows * 128;
    unsigned short* th = dhi + (size_t)nt * elems;
    unsigned short* tl = dlo + (size_t)nt * elems;
    for (int idx = threadIdx.x; idx < elems; idx += 256) {
        const int nl = idx >> 7, k = idx & 127;
        const int n = nt * ntileRows + nl;
        float v = (k < Ksrc) ? src[(size_t)k * Nsrc + n] : 0.f;
        unsigned short h, l;
        split_bf16(v, h, l);
        th[nl * 128 + k] = h;
        tl[nl * 128 + k] = l;
    }
}

// prep3: j=0: CyT -> YB rows 0-63 ; j=1: ACyT -> YB rows 64-127 ; j=2: KC -> KCT.
__global__ __launch_bounds__(256) void prep3(const float* __restrict__ CyT) {
    const int j = blockIdx.x;
    const float* src = (j == 0) ? CyT : (j == 1) ? g_ACyT : g_KC;
    const int Ksrc = (j == 2) ? 64 : 128;
    unsigned short* th = (j == 0) ? g_YB_hi : (j == 1) ? (g_YB_hi + 64 * 128) : g_KCT_hi;
    unsigned short* tl = (j == 0) ? g_YB_lo : (j == 1) ? (g_YB_lo + 64 * 128) : g_KCT_lo;
    for (int idx = threadIdx.x; idx < 64 * 128; idx += 256) {
        const int nl = idx >> 7, k = idx & 127;
        float v = (k < Ksrc) ? src[(size_t)k * 64 + nl] : 0.f;
        unsigned short h, l;
        split_bf16(v, h, l);
        th[nl * 128 + k] = h;
        tl[nl * 128 + k] = l;
    }
}

// ---------------------------------------------------------------------------
// hgemm (verified R13): D[64, NTILE] = A[64,128] @ B^T, split-bf16.
// MODE 0: write g_Z. MODE 1: write y. MODE 4: y[2i] += x@KC.
// MODE 5: odd += S@CyT ; even+2 += S@ACyT.
// ---------------------------------------------------------------------------
template <int NTILE, int MODE>
__global__ __launch_bounds__(256) void hgemm(const float* __restrict__ gA,
                                             const unsigned short* __restrict__ gBhi,
                                             const unsigned short* __restrict__ gBlo,
                                             float* __restrict__ out) {
    extern __shared__ __align__(16) char smc[];
    constexpr int A_ELE = MROWS * SSTRIDE;
    constexpr int B_ELE = NTILE * SSTRIDE;
    unsigned short* sAhi = (unsigned short*)smc;
    unsigned short* sAlo = sAhi + A_ELE;
    unsigned short* sBhi = sAlo + A_ELE;
    unsigned short* sBlo = sBhi + B_ELE;
    const uint32_t aAhi = smem_u32(sAhi), aAlo = smem_u32(sAlo);
    const uint32_t aBhi = smem_u32(sBhi), aBlo = smem_u32(sBlo);

    const int t = threadIdx.x;
    const int lane = t & 31, w = t >> 5;

    {
        const float4* Atile = (const float4*)(gA + (size_t)blockIdx.x * (MROWS * 128));
#pragma unroll
        for (int j = 0; j < 8; j++) {
            const int f = j * 256 + t;
            const float4 v = Atile[f];
            const int row = f >> 5, c = (f & 31) * 4;
            unsigned short h0, l0, h1, l1, h2, l2, h3, l3;
            split_bf16(v.x, h0, l0);
            split_bf16(v.y, h1, l1);
            split_bf16(v.z, h2, l2);
            split_bf16(v.w, h3, l3);
            const unsigned long long hh =
                (unsigned long long)h0 | ((unsigned long long)h1 << 16) |
                ((unsigned long long)h2 << 32) | ((unsigned long long)h3 << 48);
            const unsigned long long ll =
                (unsigned long long)l0 | ((unsigned long long)l1 << 16) |
                ((unsigned long long)l2 << 32) | ((unsigned long long)l3 << 48);
            *(unsigned long long*)(sAhi + row * SSTRIDE + c) = hh;
            *(unsigned long long*)(sAlo + row * SSTRIDE + c) = ll;
        }
    }
    {
        const size_t boff = (MODE == 1) ? (size_t)blockIdx.y * (NTILE * 128) : 0;
        const uint4* sh = (const uint4*)(gBhi + boff);
        const uint4* sl = (const uint4*)(gBlo + boff);
#pragma unroll
        for (int j = 0; j < NTILE / 16; j++) {
            const int f = j * 256 + t;
            const int row = f >> 4, c = (f & 15) * 8;
            *(uint4*)(sBhi + row * SSTRIDE + c) = sh[f];
            *(uint4*)(sBlo + row * SSTRIDE + c) = sl[f];
        }
    }
    __syncthreads();

    const int wm = w & 1, wn = w >> 1;
    const int m0w = wm * 32, n0w = wn * (NTILE / 4);
    constexpr int NF = NTILE / 32;

    float acc[2][NF][4];
#pragma unroll
    for (int i = 0; i < 2; i++)
#pragma unroll
        for (int j = 0; j < NF; j++)
#pragma unroll
            for (int q = 0; q < 4; q++) acc[i][j][q] = 0.f;

    const int aRow = lane & 15, aCol = (lane >> 4) * 8;
    const int bRow = (lane & 7) + ((lane >> 4) << 3), bCol = ((lane >> 3) & 1) * 8;

#pragma unroll
    for (int ks = 0; ks < 8; ks++) {
        const int k0 = ks * 16;
        uint32_t ahi[2][4], alo[2][4];
#pragma unroll
        for (int mf = 0; mf < 2; mf++) {
            const uint32_t off =
                (uint32_t)(((m0w + mf * 16 + aRow) * SSTRIDE + k0 + aCol) * 2);
            ldsm4(aAhi + off, ahi[mf]);
            ldsm4(aAlo + off, alo[mf]);
        }
        uint32_t bhi[NF][2], blo[NF][2];
#pragma unroll
        for (int nf2 = 0; nf2 < NF / 2; nf2++) {
            const uint32_t off =
                (uint32_t)(((n0w + nf2 * 16 + bRow) * SSTRIDE + k0 + bCol) * 2);
            uint32_t r[4];
            ldsm4(aBhi + off, r);
            bhi[nf2 * 2][0] = r[0]; bhi[nf2 * 2][1] = r[1];
            bhi[nf2 * 2 + 1][0] = r[2]; bhi[nf2 * 2 + 1][1] = r[3];
            ldsm4(aBlo + off, r);
            blo[nf2 * 2][0] = r[0]; blo[nf2 * 2][1] = r[1];
            blo[nf2 * 2 + 1][0] = r[2]; blo[nf2 * 2 + 1][1] = r[3];
        }
#pragma unroll
        for (int mf = 0; mf < 2; mf++)
#pragma unroll
            for (int nf = 0; nf < NF; nf++) {
                mma16816(acc[mf][nf], ahi[mf], bhi[nf]);
                mma16816(acc[mf][nf], ahi[mf], blo[nf]);
                mma16816(acc[mf][nf], alo[mf], bhi[nf]);
            }
    }

#pragma unroll
    for (int mf = 0; mf < 2; mf++) {
#pragma unroll
        for (int half = 0; half < 2; half++) {
            const int rloc = m0w + mf * 16 + (lane >> 2) + half * 8;
            const int r = blockIdx.x * MROWS + rloc;

            if (MODE == 5) {
                const int b = r >> 11, i = r & (HT - 1);
                const bool lastI = ((i & (HCH - 1)) == (HCH - 1));
                float* base1 = out + ((size_t)b * T_ + 2 * i + 1) * NOUT;
                float* base2 = out + ((size_t)b * T_ + 2 * i + 2) * NOUT;
#pragma unroll
                for (int nf = 0; nf < NF; nf++) {
                    const int n = n0w + nf * 8 + (lane & 3) * 2;
                    float* p;
                    if (n < 64) p = base1 + n;
                    else { if (lastI) continue; p = base2 + (n - 64); }
                    float2 v = make_float2(acc[mf][nf][half * 2],
                                           acc[mf][nf][half * 2 + 1]);
                    float2 e = *(float2*)p;
                    v.x += e.x; v.y += e.y;
                    *(float2*)p = v;
                }
                continue;
            }

            float* rowp;
            bool doacc = false;
            if (MODE == 0) {
                rowp = out + (size_t)r * 128;
            } else if (MODE == 1) {
                rowp = out + (size_t)r * 4096 + blockIdx.y * 128;
            } else {  // MODE 4
                const int b = r >> 11, i = r & (HT - 1);
                rowp = out + ((size_t)b * T_ + 2 * i) * NOUT;
                doacc = true;
            }
#pragma unroll
            for (int nf = 0; nf < NF; nf++) {
                const int cc = n0w + nf * 8 + (lane & 3) * 2;
                float2 v = make_float2(acc[mf][nf][half * 2],
                                       acc[mf][nf][half * 2 + 1]);
                float* p = rowp + cc;
                if (doacc) {
                    float2 e = *(float2*)p;
                    v.x += e.x; v.y += e.y;
                }
                *(float2*)p = v;
            }
        }
    }
}

// ---------------------------------------------------------------------------
// Small kernels
// ---------------------------------------------------------------------------
__global__ __launch_bounds__(128) void matsq(const float* __restrict__ A,
                                             float* __restrict__ O) {
    const int r = blockIdx.x, u = threadIdx.x;
    __shared__ float row[U_];
    row[u] = A[r * U_ + u];
    __syncthreads();
    float a0 = 0.f, a1 = 0.f, a2 = 0.f, a3 = 0.f;
#pragma unroll
    for (int k = 0; k < U_; k += 4) {
        a0 = fmaf(row[k + 0], A[(k + 0) * U_ + u], a0);
        a1 = fmaf(row[k + 1], A[(k + 1) * U_ + u], a1);
        a2 = fmaf(row[k + 2], A[(k + 2) * U_ + u], a2);
        a3 = fmaf(row[k + 3], A[(k + 3) * U_ + u], a3);
    }
    O[r * U_ + u] = (a0 + a1) + (a2 + a3);
}

__global__ __launch_bounds__(128) void buildM(const float* __restrict__ KT,
                                              const float* __restrict__ A) {
    const int r = blockIdx.x, u = threadIdx.x;
    __shared__ float row[U_];
    row[u] = KT[r * U_ + u];
    __syncthreads();
    float a0 = 0.f, a1 = 0.f, a2 = 0.f, a3 = 0.f;
#pragma unroll
    for (int k = 0; k < U_; k += 4) {
        a0 = fmaf(row[k + 0], A[(k + 0) * U_ + u], a0);
        a1 = fmaf(row[k + 1], A[(k + 1) * U_ + u], a1);
        a2 = fmaf(row[k + 2], A[(k + 2) * U_ + u], a2);
        a3 = fmaf(row[k + 3], A[(k + 3) * U_ + u], a3);
    }
    g_M[r * U_ + u] = (a0 + a1) + (a2 + a3);
    g_M[(64 + r) * U_ + u] = row[u];
}

__global__ __launch_bounds__(64) void buildSmall(const float* __restrict__ KT,
                                                 const float* __restrict__ A,
                                                 const float* __restrict__ CyT) {
    const int bid = blockIdx.x, o = threadIdx.x;
    __shared__ float row[U_];
    const float* src = (bid < 64) ? (KT + (size_t)bid * U_)
                                  : (A + (size_t)(bid - 64) * U_);
    row[o] = src[o];
    row[o + 64] = src[o + 64];
    __syncthreads();
    float a0 = 0.f, a1 = 0.f, a2 = 0.f, a3 = 0.f;
#pragma unroll
    for (int k = 0; k < U_; k += 4) {
        a0 = fmaf(row[k + 0], CyT[(k + 0) * NOUT + o], a0);
        a1 = fmaf(row[k + 1], CyT[(k + 1) * NOUT + o], a1);
        a2 = fmaf(row[k + 2], CyT[(k + 2) * NOUT + o], a2);
        a3 = fmaf(row[k + 3], CyT[(k + 3) * NOUT + o], a3);
    }
    const float v = (a0 + a1) + (a2 + a3);
    if (bid < 64) g_KC[bid * NOUT + o] = v;
    else          g_ACyT[(bid - 64) * NOUT + o] = v;
}

// ---------------------------------------------------------------------------
// scan v2: 256 threads = 2 independent 8-batch groups sharing one smem A2 copy.
// grid (64 chunks, 4) = 256 CTAs x 8 warps -> ~14 warps/SM (was ~7).
// e_i = Z_i + e_{i-1}@A2, 32 steps. Same per-element accumulation order.
// ---------------------------------------------------------------------------
__global__ __launch_bounds__(256) void scan_kernel(const float* __restrict__ A2) {
    extern __shared__ __align__(16) float sm[];
    float* a2 = sm;                      // 16384 floats (64KB)
    const int t = threadIdx.x;
    const int g = t >> 7, u = t & 127;
    float* sbuf = sm + 16384 + g * 2048; // 2 bufs x 1024 floats per group
    const int c = blockIdx.x;
    const int b0 = (blockIdx.y * 2 + g) * 8;

    for (int i = t; i < 16384; i += 256) a2[i] = A2[i];
#pragma unroll
    for (int j = 0; j < 8; j++) sbuf[u * 8 + j] = 0.f;
    __syncthreads();

    const int i0 = c * HCH;
    float zc[8];
#pragma unroll
    for (int j = 0; j < 8; j++)
        zc[j] = g_Z[((size_t)(b0 + j) * HT + i0) * U_ + u];

    int p = 0;
#pragma unroll 1
    for (int it = 0; it < HCH; it++) {
        const int i = i0 + it;
        float zn[8];
        if (it < HCH - 1) {
#pragma unroll
            for (int j = 0; j < 8; j++)
                zn[j] = g_Z[((size_t)(b0 + j) * HT + i + 1) * U_ + u];
        } else {
#pragma unroll
            for (int j = 0; j < 8; j++) zn[j] = 0.f;
        }

        unsigned long long acc[4];
#pragma unroll
        for (int q = 0; q < 4; q++) acc[q] = pack2(zc[2 * q], zc[2 * q + 1]);

        const float* sp = sbuf + p * 1024;
#pragma unroll
        for (int k = 0; k < U_; k++) {
            const unsigned long long av = dup2(a2[k * U_ + u]);
            const ulonglong2 s01 = *(const ulonglong2*)&sp[k * 8];
            const ulonglong2 s23 = *(const ulonglong2*)&sp[k * 8 + 4];
            acc[0] = ffma2(s01.x, av, acc[0]);
            acc[1] = ffma2(s01.y, av, acc[1]);
            acc[2] = ffma2(s23.x, av, acc[2]);
            acc[3] = ffma2(s23.y, av, acc[3]);
        }

        const int q = p ^ 1;
        float2 f0 = unpack2(acc[0]), f1 = unpack2(acc[1]);
        float2 f2 = unpack2(acc[2]), f3 = unpack2(acc[3]);
        {
            float4* dst = (float4*)&sbuf[q * 1024 + u * 8];
            dst[0] = make_float4(f0.x, f0.y, f1.x, f1.y);
            dst[1] = make_float4(f2.x, f2.y, f3.x, f3.y);
        }
        g_S[((size_t)(b0 + 0) * HT + i) * U_ + u] = f0.x;
        g_S[((size_t)(b0 + 1) * HT + i) * U_ + u] = f0.y;
        g_S[((size_t)(b0 + 2) * HT + i) * U_ + u] = f1.x;
        g_S[((size_t)(b0 + 3) * HT + i) * U_ + u] = f1.y;
        g_S[((size_t)(b0 + 4) * HT + i) * U_ + u] = f2.x;
        g_S[((size_t)(b0 + 5) * HT + i) * U_ + u] = f2.y;
        g_S[((size_t)(b0 + 6) * HT + i) * U_ + u] = f3.x;
        g_S[((size_t)(b0 + 7) * HT + i) * U_ + u] = f3.y;
        __syncthreads();

        p = q;
#pragma unroll
        for (int j = 0; j < 8; j++) zc[j] = zn[j];
    }
}

__global__ __launch_bounds__(128) void pass2_kernel() {
    const int b = blockIdx.x, u = threadIdx.x;
    __shared__ float ss[2][U_];
    float m[U_];
#pragma unroll
    for (int k = 0; k < U_; k++) m[k] = g_A64[k * U_ + u];

    float su = 0.f;
    float e = g_S[((size_t)b * HT + (HCH - 1)) * U_ + u];
    ss[0][u] = 0.f;
    __syncthreads();

    int p = 0;
#pragma unroll 1
    for (int c = 0; c < CCH; c++) {
        g_carry[((size_t)b * CCH + c) * U_ + u] = su;
        float a0 = e, a1 = 0.f, a2 = 0.f, a3 = 0.f;
        if (c < CCH - 1)
            e = g_S[((size_t)b * HT + (c + 1) * HCH + (HCH - 1)) * U_ + u];
#pragma unroll
        for (int k = 0; k < U_; k += 4) {
            a0 = fmaf(ss[p][k + 0], m[k + 0], a0);
            a1 = fmaf(ss[p][k + 1], m[k + 1], a1);
            a2 = fmaf(ss[p][k + 2], m[k + 2], a2);
            a3 = fmaf(ss[p][k + 3], m[k + 3], a3);
        }
        su = (a0 + a1) + (a2 + a3);
        ss[p ^ 1][u] = su;
        __syncthreads();
        p ^= 1;
    }
}

// ---------------------------------------------------------------------------
// wbuild (verified): W[s] = A^(s+1)@CyT, direct split write
// ---------------------------------------------------------------------------
__global__ __launch_bounds__(512) void wbuild(const float* __restrict__ A1,
                                              const float* __restrict__ CyT) {
    extern __shared__ float V[];
    float* cur = V;
    float* nxt = V + 8192;
    const int s = blockIdx.x;
    const int n = s + 1;
    const int tid = threadIdx.x;
    const int o = tid & 63, kg = tid >> 6;

    for (int i = tid; i < U_ * NOUT; i += 512) cur[i] = CyT[i];
    __syncthreads();

#pragma unroll 1
    for (int b = 0; b < 7; b++) {
        if (!((n >> b) & 1)) continue;
        const float* P = (b == 0) ? A1
                       : (b == 1) ? g_A2  : (b == 2) ? g_A4
                       : (b == 3) ? g_A8  : (b == 4) ? g_A16
                       : (b == 5) ? g_A32 : g_A64;
#pragma unroll 1
        for (int i = 0; i < 16; i++) {
            const int k = kg * 16 + i;
            float a0 = 0.f, a1 = 0.f, a2 = 0.f, a3 = 0.f;
#pragma unroll
            for (int m = 0; m < U_; m += 4) {
                a0 = fmaf(P[k * U_ + m + 0], cur[(m + 0) * 64 + o], a0);
                a1 = fmaf(P[k * U_ + m + 1], cur[(m + 1) * 64 + o], a1);
                a2 = fmaf(P[k * U_ + m + 2], cur[(m + 2) * 64 + o], a2);
                a3 = fmaf(P[k * U_ + m + 3], cur[(m + 3) * 64 + o], a3);
            }
            nxt[k * 64 + o] = (a0 + a1) + (a2 + a3);
        }
        __syncthreads();
        float* tmp = cur; cur = nxt; nxt = tmp;
    }

    {
        unsigned short* th = g_WT_hi + (size_t)(s >> 1) * 16384;
        unsigned short* tl = g_WT_lo + (size_t)(s >> 1) * 16384;
        const int nbase = (s & 1) * 64;
#pragma unroll 1
        for (int idx = tid; idx < 8192; idx += 512) {
            const int k = idx & 127, oo = idx >> 7;
            unsigned short h, l;
            split_bf16(cur[k * 64 + oo], h, l);
            th[(nbase + oo) * 128 + k] = h;
            tl[(nbase + oo) * 128 + k] = l;
        }
    }
}

// ---------------------------------------------------------------------------
// Launch (R13 order).  #4 = hgemm<128,0> anchor; #5 = scan v2.
// ---------------------------------------------------------------------------
extern "C" void kernel_launch(void* const* d_in, const int* in_sizes, int n_in,
                              void* d_out, int out_size) {
    const float* x   = (const float*)d_in[0];
    const float* AT  = (const float*)d_in[1];
    const float* KT  = (const float*)d_in[2];
    const float* CyT = (const float*)d_in[3];
    float* y = (float*)d_out;

    float *A2, *A4, *A8, *A16, *A32, *A64, *pM, *pZ, *pS, *pCar;
    unsigned short *MTh, *MTl, *WTh, *WTl, *YBh, *YBl, *KCTh, *KCTl;
    cudaGetSymbolAddress((void**)&A2,  g_A2);
    cudaGetSymbolAddress((void**)&A4,  g_A4);
    cudaGetSymbolAddress((void**)&A8,  g_A8);
    cudaGetSymbolAddress((void**)&A16, g_A16);
    cudaGetSymbolAddress((void**)&A32, g_A32);
    cudaGetSymbolAddress((void**)&A64, g_A64);
    cudaGetSymbolAddress((void**)&pM,  g_M);
    cudaGetSymbolAddress((void**)&pZ,  g_Z);
    cudaGetSymbolAddress((void**)&pS,  g_S);
    cudaGetSymbolAddress((void**)&pCar, g_carry);
    cudaGetSymbolAddress((void**)&MTh, g_MT_hi);  cudaGetSymbolAddress((void**)&MTl, g_MT_lo);
    cudaGetSymbolAddress((void**)&WTh, g_WT_hi);  cudaGetSymbolAddress((void**)&WTl, g_WT_lo);
    cudaGetSymbolAddress((void**)&YBh, g_YB_hi);  cudaGetSymbolAddress((void**)&YBl, g_YB_lo);
    cudaGetSymbolAddress((void**)&KCTh, g_KCT_hi); cudaGetSymbolAddress((void**)&KCTl, g_KCT_lo);

    const int SM128 = (2 * MROWS * SSTRIDE + 2 * 128 * SSTRIDE) * 2;  // 104448
    const int SM64  = (2 * MROWS * SSTRIDE + 2 * 64 * SSTRIDE) * 2;   // 69632
    const int SMSCAN = (16384 + 4096) * 4;                            // 81920
    cudaFuncSetAttribute(hgemm<128, 0>, cudaFuncAttributeMaxDynamicSharedMemorySize, SM128);
    cudaFuncSetAttribute(hgemm<128, 1>, cudaFuncAttributeMaxDynamicSharedMemorySize, SM128);
    cudaFuncSetAttribute(hgemm<128, 5>, cudaFuncAttributeMaxDynamicSharedMemorySize, SM128);
    cudaFuncSetAttribute(hgemm<64, 4>,  cudaFuncAttributeMaxDynamicSharedMemorySize, SM64);
    cudaFuncSetAttribute(scan_kernel, cudaFuncAttributeMaxDynamicSharedMemorySize, SMSCAN);
    cudaFuncSetAttribute(wbuild, cudaFuncAttributeMaxDynamicSharedMemorySize, 65536);

    buildM<<<64, 128>>>(KT, AT);                               // 1
    matsq<<<128, 128>>>(AT, A2);                               // 2
    prepB<<<1, 256>>>(pM, 128, 128, MTh, MTl, 128);            // 3
    hgemm<128, 0><<<2048, 256, SM128>>>(x, MTh, MTl, pZ);      // 4  <- ncu anchor
    scan_kernel<<<dim3(CCH, 4), 256, SMSCAN>>>(A2);            // 5  (scan v2)
    matsq<<<128, 128>>>(A2,  A4);                              // 6
    matsq<<<128, 128>>>(A4,  A8);                              // 7
    matsq<<<128, 128>>>(A8,  A16);                             // 8
    matsq<<<128, 128>>>(A16, A32);                             // 9
    matsq<<<128, 128>>>(A32, A64);                             // 10
    buildSmall<<<192, 64>>>(KT, AT, CyT);                      // 11
    prep3<<<3, 256>>>(CyT);                                    // 12
    pass2_kernel<<<B_, 128>>>();                               // 13
    wbuild<<<LCH, 512, 65536>>>(AT, CyT);                      // 14
    hgemm<128, 1><<<dim3(64, 32), 256, SM128>>>(pCar, WTh, WTl, y);  // 15 (writes y)
    hgemm<64, 4><<<2048, 256, SM64>>>(x,  KCTh, KCTl, y);      // 16 (+= even)
    hgemm<128, 5><<<2048, 256, SM128>>>(pS, YBh, YBl, y);      // 17 (+= odd & even+2)
}

// round 17
// speedup vs baseline: 1.4509x; 1.0165x over previous
#include <cuda_runtime.h>
#include <cuda_bf16.h>
#include <cstdint>

#define B_   64
#define T_   4096
#define NIN  64
#define U_   128
#define NOUT 64
#define CCH  64
#define LCH  64
#define HT   2048
#define HCH  32

#define SSTRIDE 136
#define MROWS   64

// ---------------------------------------------------------------------------
// Static device scratch
// ---------------------------------------------------------------------------
__device__ float g_Z[B_ * HT * U_];
__device__ float g_S[B_ * HT * U_];
__device__ float g_carry[B_ * CCH * U_];
__device__ float g_M[U_ * U_];
__device__ float g_KC[NIN * NOUT];
__device__ float g_ACyT[U_ * NOUT];
__device__ float g_A2[U_ * U_], g_A4[U_ * U_], g_A8[U_ * U_];
__device__ float g_A16[U_ * U_], g_A32[U_ * U_], g_A64[U_ * U_];

__device__ __align__(16) unsigned short g_MT_hi[128 * 128],  g_MT_lo[128 * 128];
__device__ __align__(16) unsigned short g_WT_hi[32 * 128 * 128], g_WT_lo[32 * 128 * 128];
__device__ __align__(16) unsigned short g_YB_hi[128 * 128],  g_YB_lo[128 * 128];
__device__ __align__(16) unsigned short g_KCT_hi[64 * 128],  g_KCT_lo[64 * 128];

// ---------------------------------------------------------------------------
// f32x2 helpers
// ---------------------------------------------------------------------------
__device__ __forceinline__ unsigned long long ffma2(unsigned long long a,
                                                    unsigned long long b,
                                                    unsigned long long c) {
    unsigned long long d;
    asm("fma.rn.f32x2 %0, %1, %2, %3;" : "=l"(d) : "l"(a), "l"(b), "l"(c));
    return d;
}
__device__ __forceinline__ unsigned long long dup2(float v) {
    unsigned long long r;
    asm("mov.b64 %0, {%1, %1};" : "=l"(r) : "f"(v));
    return r;
}
__device__ __forceinline__ unsigned long long pack2(float x, float y) {
    unsigned long long r;
    asm("mov.b64 %0, {%1, %2};" : "=l"(r) : "f"(x), "f"(y));
    return r;
}
__device__ __forceinline__ float2 unpack2(unsigned long long v) {
    float2 f;
    asm("mov.b64 {%0, %1}, %2;" : "=f"(f.x), "=f"(f.y) : "l"(v));
    return f;
}

// ---------------------------------------------------------------------------
// mma.sync / ldmatrix helpers
// ---------------------------------------------------------------------------
__device__ __forceinline__ uint32_t smem_u32(const void* p) {
    uint32_t a;
    asm("{ .reg .u64 t; cvta.to.shared.u64 t, %1; cvt.u32.u64 %0, t; }"
        : "=r"(a) : "l"(p));
    return a;
}

__device__ __forceinline__ void ldsm4(uint32_t addr, uint32_t r[4]) {
    asm volatile("ldmatrix.sync.aligned.m8n8.x4.shared.b16 {%0,%1,%2,%3}, [%4];"
                 : "=r"(r[0]), "=r"(r[1]), "=r"(r[2]), "=r"(r[3]) : "r"(addr));
}

__device__ __forceinline__ void mma16816(float c[4], const uint32_t a[4],
                                         const uint32_t b[2]) {
    asm volatile(
        "mma.sync.aligned.m16n8k16.row.col.f32.bf16.bf16.f32 "
        "{%0,%1,%2,%3}, {%4,%5,%6,%7}, {%8,%9}, {%0,%1,%2,%3};"
        : "+f"(c[0]), "+f"(c[1]), "+f"(c[2]), "+f"(c[3])
        : "r"(a[0]), "r"(a[1]), "r"(a[2]), "r"(a[3]), "r"(b[0]), "r"(b[1]));
}

__device__ __forceinline__ void split_bf16(float v, unsigned short& h, unsigned short& l) {
    __nv_bfloat16 hb = __float2bfloat16(v);
    float r = v - __bfloat162float(hb);
    __nv_bfloat16 lb = __float2bfloat16(r);
    h = *reinterpret_cast<unsigned short*>(&hb);
    l = *reinterpret_cast<unsigned short*>(&lb);
}

// ---------------------------------------------------------------------------
// prepB (small matrices)
// ---------------------------------------------------------------------------
__global__ __launch_bounds__(256) void prepB(const float* __restrict__ src,
                                             int Ksrc, int Nsrc,
                                             unsigned short* __restrict__ dhi,
                                             unsigned short* __restrict__ dlo,
                                             int ntileRows) {
    const int nt = blockIdx.x;
    const int elems = ntileRows * 128;
    unsigned short* th = dhi + (size_t)nt * elems;
    unsigned short* tl = dlo + (size_t)nt * elems;
    for (int idx = threadIdx.x; idx < elems; idx += 256) {
        const int nl = idx >> 7, k = idx & 127;
        const int n = nt * ntileRows + nl;
        float v = (k < Ksrc) ? src[(size_t)k * Nsrc + n] : 0.f;
        unsigned short h, l;
        split_bf16(v, h, l);
        th[nl * 128 + k] = h;
        tl[nl * 128 + k] = l;
    }
}

// prep3: j=0: CyT -> YB rows 0-63 ; j=1: ACyT -> YB rows 64-127 ; j=2: KC -> KCT.
__global__ __launch_bounds__(256) void prep3(const float* __restrict__ CyT) {
    const int j = blockIdx.x;
    const float* src = (j == 0) ? CyT : (j == 1) ? g_ACyT : g_KC;
    const int Ksrc = (j == 2) ? 64 : 128;
    unsigned short* th = (j == 0) ? g_YB_hi : (j == 1) ? (g_YB_hi + 64 * 128) : g_KCT_hi;
    unsigned short* tl = (j == 0) ? g_YB_lo : (j == 1) ? (g_YB_lo + 64 * 128) : g_KCT_lo;
    for (int idx = threadIdx.x; idx < 64 * 128; idx += 256) {
        const int nl = idx >> 7, k = idx & 127;
        float v = (k < Ksrc) ? src[(size_t)k * 64 + nl] : 0.f;
        unsigned short h, l;
        split_bf16(v, h, l);
        th[nl * 128 + k] = h;
        tl[nl * 128 + k] = l;
    }
}

// ---------------------------------------------------------------------------
// hgemm (verified R13): D[64, NTILE] = A[64,128] @ B^T, split-bf16.
// MODE 0: write g_Z. MODE 1: write y. MODE 4: y[2i] += x@KC.
// MODE 5: odd += S@CyT ; even+2 += S@ACyT.
// ---------------------------------------------------------------------------
template <int NTILE, int MODE>
__global__ __launch_bounds__(256) void hgemm(const float* __restrict__ gA,
                                             const unsigned short* __restrict__ gBhi,
                                             const unsigned short* __restrict__ gBlo,
                                             float* __restrict__ out) {
    extern __shared__ __align__(16) char smc[];
    constexpr int A_ELE = MROWS * SSTRIDE;
    constexpr int B_ELE = NTILE * SSTRIDE;
    unsigned short* sAhi = (unsigned short*)smc;
    unsigned short* sAlo = sAhi + A_ELE;
    unsigned short* sBhi = sAlo + A_ELE;
    unsigned short* sBlo = sBhi + B_ELE;
    const uint32_t aAhi = smem_u32(sAhi), aAlo = smem_u32(sAlo);
    const uint32_t aBhi = smem_u32(sBhi), aBlo = smem_u32(sBlo);

    const int t = threadIdx.x;
    const int lane = t & 31, w = t >> 5;

    {
        const float4* Atile = (const float4*)(gA + (size_t)blockIdx.x * (MROWS * 128));
#pragma unroll
        for (int j = 0; j < 8; j++) {
            const int f = j * 256 + t;
            const float4 v = Atile[f];
            const int row = f >> 5, c = (f & 31) * 4;
            unsigned short h0, l0, h1, l1, h2, l2, h3, l3;
            split_bf16(v.x, h0, l0);
            split_bf16(v.y, h1, l1);
            split_bf16(v.z, h2, l2);
            split_bf16(v.w, h3, l3);
            const unsigned long long hh =
                (unsigned long long)h0 | ((unsigned long long)h1 << 16) |
                ((unsigned long long)h2 << 32) | ((unsigned long long)h3 << 48);
            const unsigned long long ll =
                (unsigned long long)l0 | ((unsigned long long)l1 << 16) |
                ((unsigned long long)l2 << 32) | ((unsigned long long)l3 << 48);
            *(unsigned long long*)(sAhi + row * SSTRIDE + c) = hh;
            *(unsigned long long*)(sAlo + row * SSTRIDE + c) = ll;
        }
    }
    {
        const size_t boff = (MODE == 1) ? (size_t)blockIdx.y * (NTILE * 128) : 0;
        const uint4* sh = (const uint4*)(gBhi + boff);
        const uint4* sl = (const uint4*)(gBlo + boff);
#pragma unroll
        for (int j = 0; j < NTILE / 16; j++) {
            const int f = j * 256 + t;
            const int row = f >> 4, c = (f & 15) * 8;
            *(uint4*)(sBhi + row * SSTRIDE + c) = sh[f];
            *(uint4*)(sBlo + row * SSTRIDE + c) = sl[f];
        }
    }
    __syncthreads();

    const int wm = w & 1, wn = w >> 1;
    const int m0w = wm * 32, n0w = wn * (NTILE / 4);
    constexpr int NF = NTILE / 32;

    float acc[2][NF][4];
#pragma unroll
    for (int i = 0; i < 2; i++)
#pragma unroll
        for (int j = 0; j < NF; j++)
#pragma unroll
            for (int q = 0; q < 4; q++) acc[i][j][q] = 0.f;

    const int aRow = lane & 15, aCol = (lane >> 4) * 8;
    const int bRow = (lane & 7) + ((lane >> 4) << 3), bCol = ((lane >> 3) & 1) * 8;

#pragma unroll
    for (int ks = 0; ks < 8; ks++) {
        const int k0 = ks * 16;
        uint32_t ahi[2][4], alo[2][4];
#pragma unroll
        for (int mf = 0; mf < 2; mf++) {
            const uint32_t off =
                (uint32_t)(((m0w + mf * 16 + aRow) * SSTRIDE + k0 + aCol) * 2);
            ldsm4(aAhi + off, ahi[mf]);
            ldsm4(aAlo + off, alo[mf]);
        }
        uint32_t bhi[NF][2], blo[NF][2];
#pragma unroll
        for (int nf2 = 0; nf2 < NF / 2; nf2++) {
            const uint32_t off =
                (uint32_t)(((n0w + nf2 * 16 + bRow) * SSTRIDE + k0 + bCol) * 2);
            uint32_t r[4];
            ldsm4(aBhi + off, r);
            bhi[nf2 * 2][0] = r[0]; bhi[nf2 * 2][1] = r[1];
            bhi[nf2 * 2 + 1][0] = r[2]; bhi[nf2 * 2 + 1][1] = r[3];
            ldsm4(aBlo + off, r);
            blo[nf2 * 2][0] = r[0]; blo[nf2 * 2][1] = r[1];
            blo[nf2 * 2 + 1][0] = r[2]; blo[nf2 * 2 + 1][1] = r[3];
        }
#pragma unroll
        for (int mf = 0; mf < 2; mf++)
#pragma unroll
            for (int nf = 0; nf < NF; nf++) {
                mma16816(acc[mf][nf], ahi[mf], bhi[nf]);
                mma16816(acc[mf][nf], ahi[mf], blo[nf]);
                mma16816(acc[mf][nf], alo[mf], bhi[nf]);
            }
    }

#pragma unroll
    for (int mf = 0; mf < 2; mf++) {
#pragma unroll
        for (int half = 0; half < 2; half++) {
            const int rloc = m0w + mf * 16 + (lane >> 2) + half * 8;
            const int r = blockIdx.x * MROWS + rloc;

            if (MODE == 5) {
                const int b = r >> 11, i = r & (HT - 1);
                const bool lastI = ((i & (HCH - 1)) == (HCH - 1));
                float* base1 = out + ((size_t)b * T_ + 2 * i + 1) * NOUT;
                float* base2 = out + ((size_t)b * T_ + 2 * i + 2) * NOUT;
#pragma unroll
                for (int nf = 0; nf < NF; nf++) {
                    const int n = n0w + nf * 8 + (lane & 3) * 2;
                    float* p;
                    if (n < 64) p = base1 + n;
                    else { if (lastI) continue; p = base2 + (n - 64); }
                    float2 v = make_float2(acc[mf][nf][half * 2],
                                           acc[mf][nf][half * 2 + 1]);
                    float2 e = *(float2*)p;
                    v.x += e.x; v.y += e.y;
                    *(float2*)p = v;
                }
                continue;
            }

            float* rowp;
            bool doacc = false;
            if (MODE == 0) {
                rowp = out + (size_t)r * 128;
            } else if (MODE == 1) {
                rowp = out + (size_t)r * 4096 + blockIdx.y * 128;
            } else {  // MODE 4
                const int b = r >> 11, i = r & (HT - 1);
                rowp = out + ((size_t)b * T_ + 2 * i) * NOUT;
                doacc = true;
            }
#pragma unroll
            for (int nf = 0; nf < NF; nf++) {
                const int cc = n0w + nf * 8 + (lane & 3) * 2;
                float2 v = make_float2(acc[mf][nf][half * 2],
                                       acc[mf][nf][half * 2 + 1]);
                float* p = rowp + cc;
                if (doacc) {
                    float2 e = *(float2*)p;
                    v.x += e.x; v.y += e.y;
                }
                *(float2*)p = v;
            }
        }
    }
}

// ---------------------------------------------------------------------------
// buildMA2: grid 192. blocks 0-63: M rows (KT@A | KT). blocks 64-191: A2 rows.
// ---------------------------------------------------------------------------
__global__ __launch_bounds__(128) void buildMA2(const float* __restrict__ KT,
                                                const float* __restrict__ A,
                                                float* __restrict__ A2out) {
    const int bid = blockIdx.x, u = threadIdx.x;
    __shared__ float row[U_];
    const int r = (bid < 64) ? bid : (bid - 64);
    const float* srcrow = (bid < 64) ? (KT + (size_t)r * U_) : (A + (size_t)r * U_);
    row[u] = srcrow[u];
    __syncthreads();
    float a0 = 0.f, a1 = 0.f, a2 = 0.f, a3 = 0.f;
#pragma unroll
    for (int k = 0; k < U_; k += 4) {
        a0 = fmaf(row[k + 0], A[(k + 0) * U_ + u], a0);
        a1 = fmaf(row[k + 1], A[(k + 1) * U_ + u], a1);
        a2 = fmaf(row[k + 2], A[(k + 2) * U_ + u], a2);
        a3 = fmaf(row[k + 3], A[(k + 3) * U_ + u], a3);
    }
    const float v = (a0 + a1) + (a2 + a3);
    if (bid < 64) {
        g_M[r * U_ + u] = v;
        g_M[(64 + r) * U_ + u] = row[u];
    } else {
        A2out[r * U_ + u] = v;
    }
}

// ---------------------------------------------------------------------------
// matsq / buildSmall (verified)
// ---------------------------------------------------------------------------
__global__ __launch_bounds__(128) void matsq(const float* __restrict__ A,
                                             float* __restrict__ O) {
    const int r = blockIdx.x, u = threadIdx.x;
    __shared__ float row[U_];
    row[u] = A[r * U_ + u];
    __syncthreads();
    float a0 = 0.f, a1 = 0.f, a2 = 0.f, a3 = 0.f;
#pragma unroll
    for (int k = 0; k < U_; k += 4) {
        a0 = fmaf(row[k + 0], A[(k + 0) * U_ + u], a0);
        a1 = fmaf(row[k + 1], A[(k + 1) * U_ + u], a1);
        a2 = fmaf(row[k + 2], A[(k + 2) * U_ + u], a2);
        a3 = fmaf(row[k + 3], A[(k + 3) * U_ + u], a3);
    }
    O[r * U_ + u] = (a0 + a1) + (a2 + a3);
}

__global__ __launch_bounds__(64) void buildSmall(const float* __restrict__ KT,
                                                 const float* __restrict__ A,
                                                 const float* __restrict__ CyT) {
    const int bid = blockIdx.x, o = threadIdx.x;
    __shared__ float row[U_];
    const float* src = (bid < 64) ? (KT + (size_t)bid * U_)
                                  : (A + (size_t)(bid - 64) * U_);
    row[o] = src[o];
    row[o + 64] = src[o + 64];
    __syncthreads();
    float a0 = 0.f, a1 = 0.f, a2 = 0.f, a3 = 0.f;
#pragma unroll
    for (int k = 0; k < U_; k += 4) {
        a0 = fmaf(row[k + 0], CyT[(k + 0) * NOUT + o], a0);
        a1 = fmaf(row[k + 1], CyT[(k + 1) * NOUT + o], a1);
        a2 = fmaf(row[k + 2], CyT[(k + 2) * NOUT + o], a2);
        a3 = fmaf(row[k + 3], CyT[(k + 3) * NOUT + o], a3);
    }
    const float v = (a0 + a1) + (a2 + a3);
    if (bid < 64) g_KC[bid * NOUT + o] = v;
    else          g_ACyT[(bid - 64) * NOUT + o] = v;
}

// ---------------------------------------------------------------------------
// scan v3 (k-split): 256 threads = 2 k-half groups, each holds at[64] in regs.
// Group g: partial over k in [g*64, g*64+64) for all 16 batches -> smem;
// then finalizes batches [g*8, g*8+8): f = z + p0 + p1.
// ~110 regs -> 2 CTAs/SM -> 16 warps/SM; grid (64,4)=256 CTAs all resident.
// ---------------------------------------------------------------------------
__global__ __launch_bounds__(256) void scan_kernel(const float* __restrict__ A2) {
    __shared__ __align__(16) float s_sh[2][U_ * 16];   // 16 KB
    __shared__ __align__(16) float pp[2][U_ * 16];     // 16 KB partials
    const int t = threadIdx.x;
    const int g = t >> 7, u = t & 127;
    const int c = blockIdx.x, bg = blockIdx.y;
    const int b0 = bg * 16;
    const int bo = g * 8;

    float at[64];
#pragma unroll
    for (int j = 0; j < 64; j++) at[j] = A2[(g * 64 + j) * U_ + u];

#pragma unroll
    for (int j = 0; j < 8; j++) s_sh[0][u * 16 + bo + j] = 0.f;
    __syncthreads();

    const int i0 = c * HCH;
    float zc[8];
#pragma unroll
    for (int j = 0; j < 8; j++)
        zc[j] = g_Z[((size_t)(b0 + bo + j) * HT + i0) * U_ + u];

    int p = 0;
#pragma unroll 1
    for (int it = 0; it < HCH; it++) {
        const int i = i0 + it;
        float zn[8];
        if (it < HCH - 1) {
#pragma unroll
            for (int j = 0; j < 8; j++)
                zn[j] = g_Z[((size_t)(b0 + bo + j) * HT + i + 1) * U_ + u];
        } else {
#pragma unroll
            for (int j = 0; j < 8; j++) zn[j] = 0.f;
        }

        // partial over this group's 64 ks, all 16 batches
        unsigned long long acc[8] = {};
        const float* sp = s_sh[p];
        const int kbase = g * 64;
#pragma unroll
        for (int j = 0; j < 64; j++) {
            const unsigned long long av = dup2(at[j]);
            const int k = kbase + j;
            const ulonglong2 s0 = *(const ulonglong2*)&sp[k * 16 + 0];
            const ulonglong2 s1 = *(const ulonglong2*)&sp[k * 16 + 4];
            const ulonglong2 s2 = *(const ulonglong2*)&sp[k * 16 + 8];
            const ulonglong2 s3 = *(const ulonglong2*)&sp[k * 16 + 12];
            acc[0] = ffma2(s0.x, av, acc[0]);
            acc[1] = ffma2(s0.y, av, acc[1]);
            acc[2] = ffma2(s1.x, av, acc[2]);
            acc[3] = ffma2(s1.y, av, acc[3]);
            acc[4] = ffma2(s2.x, av, acc[4]);
            acc[5] = ffma2(s2.y, av, acc[5]);
            acc[6] = ffma2(s3.x, av, acc[6]);
            acc[7] = ffma2(s3.y, av, acc[7]);
        }
        {   // store partials
            float2 f0 = unpack2(acc[0]), f1 = unpack2(acc[1]);
            float2 f2 = unpack2(acc[2]), f3 = unpack2(acc[3]);
            float2 f4 = unpack2(acc[4]), f5 = unpack2(acc[5]);
            float2 f6 = unpack2(acc[6]), f7 = unpack2(acc[7]);
            float4* pd = (float4*)&pp[g][u * 16];
            pd[0] = make_float4(f0.x, f0.y, f1.x, f1.y);
            pd[1] = make_float4(f2.x, f2.y, f3.x, f3.y);
            pd[2] = make_float4(f4.x, f4.y, f5.x, f5.y);
            pd[3] = make_float4(f6.x, f6.y, f7.x, f7.y);
        }
        __syncthreads();

        // finalize this group's 8 batches: f = z + p0 + p1
        {
            const float4 q0 = *(const float4*)&pp[0][u * 16 + bo];
            const float4 q1 = *(const float4*)&pp[0][u * 16 + bo + 4];
            const float4 r0 = *(const float4*)&pp[1][u * 16 + bo];
            const float4 r1 = *(const float4*)&pp[1][u * 16 + bo + 4];
            const float f0 = zc[0] + q0.x + r0.x;
            const float f1 = zc[1] + q0.y + r0.y;
            const float f2 = zc[2] + q0.z + r0.z;
            const float f3 = zc[3] + q0.w + r0.w;
            const float f4 = zc[4] + q1.x + r1.x;
            const float f5 = zc[5] + q1.y + r1.y;
            const float f6 = zc[6] + q1.z + r1.z;
            const float f7 = zc[7] + q1.w + r1.w;
            float4* dst = (float4*)&s_sh[p ^ 1][u * 16 + bo];
            dst[0] = make_float4(f0, f1, f2, f3);
            dst[1] = make_float4(f4, f5, f6, f7);
            g_S[((size_t)(b0 + bo + 0) * HT + i) * U_ + u] = f0;
            g_S[((size_t)(b0 + bo + 1) * HT + i) * U_ + u] = f1;
            g_S[((size_t)(b0 + bo + 2) * HT + i) * U_ + u] = f2;
            g_S[((size_t)(b0 + bo + 3) * HT + i) * U_ + u] = f3;
            g_S[((size_t)(b0 + bo + 4) * HT + i) * U_ + u] = f4;
            g_S[((size_t)(b0 + bo + 5) * HT + i) * U_ + u] = f5;
            g_S[((size_t)(b0 + bo + 6) * HT + i) * U_ + u] = f6;
            g_S[((size_t)(b0 + bo + 7) * HT + i) * U_ + u] = f7;
        }
        __syncthreads();

        p ^= 1;
#pragma unroll
        for (int j = 0; j < 8; j++) zc[j] = zn[j];
    }
}

// ---------------------------------------------------------------------------
// pass2 / wbuild (verified)
// ---------------------------------------------------------------------------
__global__ __launch_bounds__(128) void pass2_kernel() {
    const int b = blockIdx.x, u = threadIdx.x;
    __shared__ float ss[2][U_];
    float m[U_];
#pragma unroll
    for (int k = 0; k < U_; k++) m[k] = g_A64[k * U_ + u];

    float su = 0.f;
    float e = g_S[((size_t)b * HT + (HCH - 1)) * U_ + u];
    ss[0][u] = 0.f;
    __syncthreads();

    int p = 0;
#pragma unroll 1
    for (int c = 0; c < CCH; c++) {
        g_carry[((size_t)b * CCH + c) * U_ + u] = su;
        float a0 = e, a1 = 0.f, a2 = 0.f, a3 = 0.f;
        if (c < CCH - 1)
            e = g_S[((size_t)b * HT + (c + 1) * HCH + (HCH - 1)) * U_ + u];
#pragma unroll
        for (int k = 0; k < U_; k += 4) {
            a0 = fmaf(ss[p][k + 0], m[k + 0], a0);
            a1 = fmaf(ss[p][k + 1], m[k + 1], a1);
            a2 = fmaf(ss[p][k + 2], m[k + 2], a2);
            a3 = fmaf(ss[p][k + 3], m[k + 3], a3);
        }
        su = (a0 + a1) + (a2 + a3);
        ss[p ^ 1][u] = su;
        __syncthreads();
        p ^= 1;
    }
}

__global__ __launch_bounds__(512) void wbuild(const float* __restrict__ A1,
                                              const float* __restrict__ CyT) {
    extern __shared__ float V[];
    float* cur = V;
    float* nxt = V + 8192;
    const int s = blockIdx.x;
    const int n = s + 1;
    const int tid = threadIdx.x;
    const int o = tid & 63, kg = tid >> 6;

    for (int i = tid; i < U_ * NOUT; i += 512) cur[i] = CyT[i];
    __syncthreads();

#pragma unroll 1
    for (int b = 0; b < 7; b++) {
        if (!((n >> b) & 1)) continue;
        const float* P = (b == 0) ? A1
                       : (b == 1) ? g_A2  : (b == 2) ? g_A4
                       : (b == 3) ? g_A8  : (b == 4) ? g_A16
                       : (b == 5) ? g_A32 : g_A64;
#pragma unroll 1
        for (int i = 0; i < 16; i++) {
            const int k = kg * 16 + i;
            float a0 = 0.f, a1 = 0.f, a2 = 0.f, a3 = 0.f;
#pragma unroll
            for (int m = 0; m < U_; m += 4) {
                a0 = fmaf(P[k * U_ + m + 0], cur[(m + 0) * 64 + o], a0);
                a1 = fmaf(P[k * U_ + m + 1], cur[(m + 1) * 64 + o], a1);
                a2 = fmaf(P[k * U_ + m + 2], cur[(m + 2) * 64 + o], a2);
                a3 = fmaf(P[k * U_ + m + 3], cur[(m + 3) * 64 + o], a3);
            }
            nxt[k * 64 + o] = (a0 + a1) + (a2 + a3);
        }
        __syncthreads();
        float* tmp = cur; cur = nxt; nxt = tmp;
    }

    {
        unsigned short* th = g_WT_hi + (size_t)(s >> 1) * 16384;
        unsigned short* tl = g_WT_lo + (size_t)(s >> 1) * 16384;
        const int nbase = (s & 1) * 64;
#pragma unroll 1
        for (int idx = tid; idx < 8192; idx += 512) {
            const int k = idx & 127, oo = idx >> 7;
            unsigned short h, l;
            split_bf16(cur[k * 64 + oo], h, l);
            th[(nbase + oo) * 128 + k] = h;
            tl[(nbase + oo) * 128 + k] = l;
        }
    }
}

// ---------------------------------------------------------------------------
// Launch: #4 = scan v3 (ncu-profiled slot).
// ---------------------------------------------------------------------------
extern "C" void kernel_launch(void* const* d_in, const int* in_sizes, int n_in,
                              void* d_out, int out_size) {
    const float* x   = (const float*)d_in[0];
    const float* AT  = (const float*)d_in[1];
    const float* KT  = (const float*)d_in[2];
    const float* CyT = (const float*)d_in[3];
    float* y = (float*)d_out;

    float *A2, *A4, *A8, *A16, *A32, *A64, *pM, *pZ, *pS, *pCar;
    unsigned short *MTh, *MTl, *WTh, *WTl, *YBh, *YBl, *KCTh, *KCTl;
    cudaGetSymbolAddress((void**)&A2,  g_A2);
    cudaGetSymbolAddress((void**)&A4,  g_A4);
    cudaGetSymbolAddress((void**)&A8,  g_A8);
    cudaGetSymbolAddress((void**)&A16, g_A16);
    cudaGetSymbolAddress((void**)&A32, g_A32);
    cudaGetSymbolAddress((void**)&A64, g_A64);
    cudaGetSymbolAddress((void**)&pM,  g_M);
    cudaGetSymbolAddress((void**)&pZ,  g_Z);
    cudaGetSymbolAddress((void**)&pS,  g_S);
    cudaGetSymbolAddress((void**)&pCar, g_carry);
    cudaGetSymbolAddress((void**)&MTh, g_MT_hi);  cudaGetSymbolAddress((void**)&MTl, g_MT_lo);
    cudaGetSymbolAddress((void**)&WTh, g_WT_hi);  cudaGetSymbolAddress((void**)&WTl, g_WT_lo);
    cudaGetSymbolAddress((void**)&YBh, g_YB_hi);  cudaGetSymbolAddress((void**)&YBl, g_YB_lo);
    cudaGetSymbolAddress((void**)&KCTh, g_KCT_hi); cudaGetSymbolAddress((void**)&KCTl, g_KCT_lo);

    const int SM128 = (2 * MROWS * SSTRIDE + 2 * 128 * SSTRIDE) * 2;  // 104448
    const int SM64  = (2 * MROWS * SSTRIDE + 2 * 64 * SSTRIDE) * 2;   // 69632
    cudaFuncSetAttribute(hgemm<128, 0>, cudaFuncAttributeMaxDynamicSharedMemorySize, SM128);
    cudaFuncSetAttribute(hgemm<128, 1>, cudaFuncAttributeMaxDynamicSharedMemorySize, SM128);
    cudaFuncSetAttribute(hgemm<128, 5>, cudaFuncAttributeMaxDynamicSharedMemorySize, SM128);
    cudaFuncSetAttribute(hgemm<64, 4>,  cudaFuncAttributeMaxDynamicSharedMemorySize, SM64);
    cudaFuncSetAttribute(wbuild, cudaFuncAttributeMaxDynamicSharedMemorySize, 65536);

    buildMA2<<<192, 128>>>(KT, AT, A2);                        // 1 (M + A2)
    prepB<<<1, 256>>>(pM, 128, 128, MTh, MTl, 128);            // 2
    hgemm<128, 0><<<2048, 256, SM128>>>(x, MTh, MTl, pZ);      // 3 (zbuild)
    scan_kernel<<<dim3(CCH, 4), 256>>>(A2);                    // 4 <- ncu (scan v3)
    matsq<<<128, 128>>>(A2,  A4);                              // 5
    matsq<<<128, 128>>>(A4,  A8);                              // 6
    matsq<<<128, 128>>>(A8,  A16);                             // 7
    matsq<<<128, 128>>>(A16, A32);                             // 8
    matsq<<<128, 128>>>(A32, A64);                             // 9
    buildSmall<<<192, 64>>>(KT, AT, CyT);                      // 10
    prep3<<<3, 256>>>(CyT);                                    // 11
    pass2_kernel<<<B_, 128>>>();                               // 12
    wbuild<<<LCH, 512, 65536>>>(AT, CyT);                      // 13
    hgemm<128, 1><<<dim3(64, 32), 256, SM128>>>(pCar, WTh, WTl, y);  // 14 (writes y)
    hgemm<64, 4><<<2048, 256, SM64>>>(x,  KCTh, KCTl, y);      // 15 (+= even)
    hgemm<128, 5><<<2048, 256, SM128>>>(pS, YBh, YBl, y);      // 16 (+= odd & even+2)
}